// round 13
// baseline (speedup 1.0000x reference)
#include <cuda_runtime.h>
#include <cuda_fp16.h>
#include <cstdint>

// Problem constants
#define B_ 4
#define T_ 2048
#define DIM_ 2048
#define H_ 16
#define QLORA_ 1536
#define KVLORA_ 512
#define MTOK (B_ * T_)   // 8192
#define NQKV 2112        // merged q_down(1536) + kv_down(576) output width

// ---------------- scratch (device globals; no runtime allocation) -------------
__device__ __half g_xh[(size_t)MTOK * DIM_];
__device__ __half g_cqkv[(size_t)MTOK * NQKV];        // merged: [cq 1536 | ckv 512 | rope 64]
__device__ float  g_rq[MTOK];                          // per-token rms scale (q)
__device__ float  g_rkv[MTOK];                         // per-token rms scale (kv)
__device__ __half g_qh[(size_t)MTOK * 3072];          // q_up out (half, scaled, roped)
__device__ __half g_kropeh[(size_t)MTOK * 64];
__device__ __half g_kvh[(size_t)MTOK * 4096];         // per head [K128|V128]
__device__ __half g_attnoh[(size_t)MTOK * 2048];
__device__ __half g_wqkd[(size_t)NQKV * DIM_];        // merged q_down + kv_down weights
__device__ __half g_wqu[(size_t)3072 * QLORA_];       // head-interleaved, pre-scaled, w-folded
__device__ __half g_wku[(size_t)4096 * KVLORA_];      // kv_norm_w folded per column
__device__ __half g_wwo[(size_t)DIM_ * 2048];

// ---------------- helpers ------------------------------------------------------
__device__ __forceinline__ float block_reduce_sum_256(float v) {
    __shared__ float red[8];
    int lane = threadIdx.x & 31, w = threadIdx.x >> 5;
#pragma unroll
    for (int o = 16; o; o >>= 1) v += __shfl_xor_sync(0xffffffffu, v, o);
    if (lane == 0) red[w] = v;
    __syncthreads();
    if (w == 0) {
        v = (lane < 8) ? red[lane] : 0.f;
#pragma unroll
        for (int o = 4; o; o >>= 1) v += __shfl_xor_sync(0xffffffffu, v, o);
        if (lane == 0) red[0] = v;
    }
    __syncthreads();
    return red[0];
}

__device__ __forceinline__ float ex2(float x) {
    float r;
    asm("ex2.approx.ftz.f32 %0, %1;" : "=f"(r) : "f"(x));
    return r;
}
__device__ __forceinline__ uint32_t smem_u32(const void* p) {
    uint32_t a;
    asm("{ .reg .u64 t; cvta.to.shared.u64 t, %1; cvt.u32.u64 %0, t; }"
        : "=r"(a) : "l"(p));
    return a;
}
__device__ __forceinline__ uint32_t packh2(float a, float b) {
    __half2 h = __floats2half2_rn(a, b);
    return *(uint32_t*)&h;
}
__device__ __forceinline__ uint2 pack4(float4 v) {
    return make_uint2(packh2(v.x, v.y), packh2(v.z, v.w));
}

#define LDMX4(r, addr) \
    asm volatile("ldmatrix.sync.aligned.m8n8.x4.shared.b16 {%0,%1,%2,%3}, [%4];" \
        : "=r"((r)[0]), "=r"((r)[1]), "=r"((r)[2]), "=r"((r)[3]) : "r"(addr))
#define LDMX4T(r, addr) \
    asm volatile("ldmatrix.sync.aligned.m8n8.x4.trans.shared.b16 {%0,%1,%2,%3}, [%4];" \
        : "=r"((r)[0]), "=r"((r)[1]), "=r"((r)[2]), "=r"((r)[3]) : "r"(addr))

__device__ __forceinline__ void mma_f16(float* c, const uint32_t* a,
                                        uint32_t b0, uint32_t b1) {
    asm volatile(
        "mma.sync.aligned.m16n8k16.row.col.f32.f16.f16.f32 "
        "{%0,%1,%2,%3},{%4,%5,%6,%7},{%8,%9},{%0,%1,%2,%3};\n"
        : "+f"(c[0]), "+f"(c[1]), "+f"(c[2]), "+f"(c[3])
        : "r"(a[0]), "r"(a[1]), "r"(a[2]), "r"(a[3]), "r"(b0), "r"(b1));
}

__device__ __forceinline__ void cpa16(uint32_t saddr, const void* src, bool v) {
    int sz = v ? 16 : 0;
    asm volatile("cp.async.cg.shared.global [%0], [%1], 16, %2;\n"
                 :: "r"(saddr), "l"(src), "r"(sz));
}

// ---------------- conversion kernels --------------------------------------------
__global__ void h_copy4(const float* __restrict__ src, __half* __restrict__ dst,
                        int S /* = n4/4 */) {
    int i = blockIdx.x * blockDim.x + threadIdx.x;
    const float4* s4 = (const float4*)src;
    uint2* d2 = (uint2*)dst;
    float4 v0 = s4[i], v1 = s4[i + S], v2 = s4[i + 2 * S], v3 = s4[i + 3 * S];
    d2[i]         = pack4(v0);
    d2[i + S]     = pack4(v1);
    d2[i + 2 * S] = pack4(v2);
    d2[i + 3 * S] = pack4(v3);
}

// q_up weights: head-interleave rows (h*192+d), fold scale*log2e AND q_norm_w[k].
#define QSC (0.07216878364870323f * 1.4426950408889634f)
__global__ void h_qup(const float* __restrict__ nope, const float* __restrict__ rope,
                      const float* __restrict__ qw, __half* __restrict__ dst) {
    int r = blockIdx.x;
    int h = r / 192, d = r - h * 192;
    const float* src = (d < 128) ? nope + (size_t)(h * 128 + d) * QLORA_
                                 : rope + (size_t)(h * 64 + d - 128) * QLORA_;
    const float4* s4 = (const float4*)src;
    const float4* w4 = (const float4*)qw;
    uint2* o2 = (uint2*)(dst + (size_t)r * QLORA_);
    int i = threadIdx.x;
#pragma unroll
    for (int j = 0; j < 3; j++) {
        int c = i + j * 128;
        float4 v = s4[c], w = w4[c];
        v.x *= QSC * w.x; v.y *= QSC * w.y; v.z *= QSC * w.z; v.w *= QSC * w.w;
        o2[c] = pack4(v);
    }
}

// kv_up weights: fold kv_norm_w per column. [4096 rows x 512 cols], 128 thr/row.
__global__ void h_wku(const float* __restrict__ src, const float* __restrict__ kw,
                      __half* __restrict__ dst) {
    int r = blockIdx.x;
    const float4* s4 = (const float4*)(src + (size_t)r * KVLORA_);
    const float4* w4 = (const float4*)kw;
    uint2* o2 = (uint2*)(dst + (size_t)r * KVLORA_);
    int i = threadIdx.x;   // 0..127
    float4 v = s4[i], w = w4[i];
    v.x *= w.x; v.y *= w.y; v.z *= w.z; v.w *= w.w;
    o2[i] = pack4(v);
}

// ---------------- fp16 tensor-core GEMM (128x128 CTA, occ 2, strided A) ---------
// Optional per-row f32 scale (rowScale) applied before the optional RoPE epilogue.
#define HAS 40                    // halves per smem row (32 + 8 pad) = 80 B
#define HTILE_B (128 * HAS * 2)   // 10240 B
#define HST_B (2 * HTILE_B)       // 20480 B
#define HST 4
#define HGEMM_SMEM (HST * HST_B)  // 81920 B

__global__ void __launch_bounds__(256, 2) hgemm(
    const __half* __restrict__ A, const __half* __restrict__ W,
    float* __restrict__ Cf, __half* __restrict__ Ch,
    int M, int N, int K, int ldc, int lda,
    const float* __restrict__ rowScale,
    int ropeOn, const float* __restrict__ fc, const float* __restrict__ fs)
{
    extern __shared__ __align__(16) char hsm[];
    uint32_t sbase = smem_u32(hsm);
    int tid = threadIdx.x, warp = tid >> 5, lane = tid & 31;
    int wm = warp >> 2, wn = warp & 3, grp = lane >> 2, qid = lane & 3;
    int bm = blockIdx.y * 128, bn = blockIdx.x * 128;

    float acc[4][4][4];
#pragma unroll
    for (int mt = 0; mt < 4; mt++)
#pragma unroll
        for (int nt = 0; nt < 4; nt++)
#pragma unroll
            for (int i = 0; i < 4; i++) acc[mt][nt][i] = 0.f;

    int lr = tid >> 2, lc = tid & 3;
    const __half* Ag0 = A + (size_t)(bm + lr) * lda + lc * 8;
    const __half* Ag1 = A + (size_t)(bm + lr + 64) * lda + lc * 8;
    int n0 = bn + lr, n1 = bn + lr + 64;
    bool v0 = n0 < N, v1 = n1 < N;
    const __half* Wg0 = W + (size_t)(v0 ? n0 : 0) * K + lc * 8;
    const __half* Wg1 = W + (size_t)(v1 ? n1 : 0) * K + lc * 8;
    uint32_t dA0 = sbase + lr * 80 + lc * 16;
    uint32_t dA1 = dA0 + 64 * 80;
    uint32_t dB0 = dA0 + HTILE_B;
    uint32_t dB1 = dB0 + 64 * 80;

    int NK = K >> 5;

    auto prefetch = [&](int kt) {
        uint32_t off = (uint32_t)((kt % HST) * HST_B);
        int ko = kt * 32;
        cpa16(dA0 + off, Ag0 + ko, true);
        cpa16(dA1 + off, Ag1 + ko, true);
        cpa16(dB0 + off, Wg0 + ko, v0);
        cpa16(dB1 + off, Wg1 + ko, v1);
    };

#pragma unroll
    for (int i = 0; i < HST - 1; i++) {
        if (i < NK) prefetch(i);
        asm volatile("cp.async.commit_group;\n");
    }

    int lrow = lane & 15;
    for (int kt = 0; kt < NK; kt++) {
        asm volatile("cp.async.wait_group 2;\n");
        __syncthreads();
        if (kt + HST - 1 < NK) prefetch(kt + HST - 1);
        asm volatile("cp.async.commit_group;\n");

        uint32_t sA = sbase + (uint32_t)((kt % HST) * HST_B);
        uint32_t sB = sA + HTILE_B;
#pragma unroll
        for (int ks = 0; ks < 2; ks++) {
            uint32_t ko = (uint32_t)((ks * 16 + 8 * (lane >> 4)) * 2);
            uint32_t a[4][4], bfr[2][4];
#pragma unroll
            for (int mt = 0; mt < 4; mt++)
                LDMX4(a[mt], sA + (uint32_t)((wm * 64 + mt * 16 + lrow) * 80) + ko);
#pragma unroll
            for (int p = 0; p < 2; p++)
                LDMX4(bfr[p], sB + (uint32_t)((wn * 32 + p * 16 + lrow) * 80) + ko);
#pragma unroll
            for (int mt = 0; mt < 4; mt++)
#pragma unroll
                for (int nt = 0; nt < 4; nt++)
                    mma_f16(acc[mt][nt], a[mt],
                            bfr[nt >> 1][nt & 1], bfr[nt >> 1][(nt & 1) + 2]);
        }
    }

#pragma unroll
    for (int mt = 0; mt < 4; mt++) {
        int row = bm + wm * 64 + mt * 16 + grp;
        int t0r = row & (T_ - 1), t1r = (row + 8) & (T_ - 1);
        float rs0 = 1.f, rs1 = 1.f;
        if (rowScale) { rs0 = rowScale[row]; rs1 = rowScale[row + 8]; }
#pragma unroll
        for (int nt = 0; nt < 4; nt++) {
            int n = bn + wn * 32 + nt * 8 + 2 * qid;
            if (n < N) {
                float o0 = acc[mt][nt][0] * rs0, o1 = acc[mt][nt][1] * rs0;
                float o2 = acc[mt][nt][2] * rs1, o3 = acc[mt][nt][3] * rs1;
                if (ropeOn) {
                    int d = n % 192;
                    if (d >= 128) {
                        int i = (d - 128) >> 1;
                        float c0 = fc[t0r * 32 + i], s0 = fs[t0r * 32 + i];
                        float c1 = fc[t1r * 32 + i], s1 = fs[t1r * 32 + i];
                        float a0 = o0 * c0 - o1 * s0, a1 = o0 * s0 + o1 * c0;
                        float a2 = o2 * c1 - o3 * s1, a3 = o2 * s1 + o3 * c1;
                        o0 = a0; o1 = a1; o2 = a2; o3 = a3;
                    }
                }
                if (Cf) {
                    *(float2*)&Cf[(size_t)row * ldc + n] = make_float2(o0, o1);
                    *(float2*)&Cf[(size_t)(row + 8) * ldc + n] = make_float2(o2, o3);
                } else {
                    *(__half2*)&Ch[(size_t)row * ldc + n] = __floats2half2_rn(o0, o1);
                    *(__half2*)&Ch[(size_t)(row + 8) * ldc + n] = __floats2half2_rn(o2, o3);
                }
            }
        }
    }
}

// ---------------- rownorm: per-token rms scales + k_rope rotation ---------------
__global__ void rownorm(const __half* __restrict__ merged,
                        const float* __restrict__ fc, const float* __restrict__ fs,
                        float* __restrict__ rq, float* __restrict__ rkv,
                        __half* __restrict__ kr) {
    int tok = blockIdx.x;
    const __half* src = merged + (size_t)tok * NQKV;
    float sq = 0.f;
    for (int i = threadIdx.x; i < QLORA_; i += 256) {
        float v = __half2float(src[i]); sq += v * v;
    }
    sq = block_reduce_sum_256(sq);
    float skv = 0.f;
    for (int i = threadIdx.x; i < KVLORA_; i += 256) {
        float v = __half2float(src[QLORA_ + i]); skv += v * v;
    }
    skv = block_reduce_sum_256(skv);
    if (threadIdx.x == 0) {
        rq[tok]  = rsqrtf(sq / (float)QLORA_ + 1e-6f);
        rkv[tok] = rsqrtf(skv / (float)KVLORA_ + 1e-6f);
    }
    if (threadIdx.x < 32) {
        int t = tok & (T_ - 1);
        int i = threadIdx.x;
        float x0 = __half2float(src[2048 + 2 * i]);
        float x1 = __half2float(src[2048 + 2 * i + 1]);
        float c = fc[t * 32 + i], s = fs[t * 32 + i];
        ((__half2*)kr)[(size_t)tok * 32 + i] =
            __floats2half2_rn(x0 * c - x1 * s, x0 * s + x1 * c);
    }
}

// ---------------- fp16 flash attention, Br=128, Bc=64, register P --------------
#define AQ 200    // halves per Q/K row (192+8); 400B stride
#define AK 200
#define AV 136    // 128+8
#define ATT_SMEM ((128*AQ + 2*64*AK + 2*64*AV) * 2)

__global__ void __launch_bounds__(256) attn2_kernel(
    const __half* __restrict__ qh, const __half* __restrict__ kvh,
    const __half* __restrict__ kroph, __half* __restrict__ out)
{
    extern __shared__ __align__(16) char smraw[];
    __half* hQ = (__half*)smraw;           // [128][AQ]
    __half* hK = hQ + 128 * AQ;            // [2][64][AK]
    __half* hV = hK + 2 * 64 * AK;         // [2][64][AV]
    uint32_t uQ = smem_u32(hQ), uK = smem_u32(hK), uV = smem_u32(hV);

    int b = blockIdx.z, h = blockIdx.y;
    int qblk = gridDim.x - 1 - blockIdx.x;   // big-work CTAs first
    int tid = threadIdx.x;
    int warp = tid >> 5, lane = tid & 31;
    int grp = lane >> 2, qid = lane & 3, lrow = lane & 15;
    int w16 = warp * 16;
    int t0 = b * T_ + qblk * 128;
    int r0 = w16 + grp, r1 = r0 + 8;

    auto prefKV = [&](int jt) {
        int kb = b * T_ + jt * 64;
        int s = jt & 1;
        uint32_t bK = uK + (uint32_t)(s * 64 * AK * 2);
        uint32_t bV = uV + (uint32_t)(s * 64 * AV * 2);
#pragma unroll
        for (int i = 0; i < 4; i++) {
            int idx = tid + i * 256, c = idx >> 4, f = idx & 15;
            cpa16(bK + (uint32_t)((c * AK + f * 8) * 2),
                  kvh + (size_t)(kb + c) * 4096 + h * 256 + f * 8, true);
        }
#pragma unroll
        for (int i = 0; i < 2; i++) {
            int idx = tid + i * 256, c = idx >> 3, f = idx & 7;
            cpa16(bK + (uint32_t)((c * AK + 128 + f * 8) * 2),
                  kroph + (size_t)(kb + c) * 64 + f * 8, true);
        }
#pragma unroll
        for (int i = 0; i < 4; i++) {
            int idx = tid + i * 256, c = idx >> 4, f = idx & 15;
            cpa16(bV + (uint32_t)((c * AV + f * 8) * 2),
                  kvh + (size_t)(kb + c) * 4096 + h * 256 + 128 + f * 8, true);
        }
    };

    int jend = 2 * qblk + 1;
    prefKV(0);
    asm volatile("cp.async.commit_group;\n");

    for (int idx = tid; idx < 128 * 24; idx += 256) {
        int r = idx / 24, f = idx - r * 24;
        *(uint4*)&hQ[r * AQ + f * 8] =
            *(const uint4*)&qh[(size_t)(t0 + r) * 3072 + h * 192 + f * 8];
    }

    float m0 = -1e30f, m1 = -1e30f, l0 = 0.f, l1 = 0.f;
    float accO[16][4];
#pragma unroll
    for (int nt = 0; nt < 16; nt++)
#pragma unroll
        for (int i = 0; i < 4; i++) accO[nt][i] = 0.f;

    for (int jt = 0; jt <= jend; jt++) {
        __syncthreads();
        if (jt < jend) prefKV(jt + 1);
        asm volatile("cp.async.commit_group;\n");
        if (jt < jend) { asm volatile("cp.async.wait_group 1;\n"); }
        else           { asm volatile("cp.async.wait_group 0;\n"); }
        __syncthreads();

        int s = jt & 1;
        uint32_t bK = uK + (uint32_t)(s * 64 * AK * 2);
        uint32_t bV = uV + (uint32_t)(s * 64 * AV * 2);

        float sfr[8][4];
#pragma unroll
        for (int nt = 0; nt < 8; nt++)
#pragma unroll
            for (int i = 0; i < 4; i++) sfr[nt][i] = 0.f;
#pragma unroll
        for (int ks = 0; ks < 12; ks++) {
            uint32_t ko = (uint32_t)((ks * 16 + 8 * (lane >> 4)) * 2);
            uint32_t a[4], bfr[4][4];
            LDMX4(a, uQ + (uint32_t)((w16 + lrow) * AQ * 2) + ko);
#pragma unroll
            for (int p = 0; p < 4; p++)
                LDMX4(bfr[p], bK + (uint32_t)((p * 16 + lrow) * AK * 2) + ko);
#pragma unroll
            for (int nt = 0; nt < 8; nt++)
                mma_f16(sfr[nt], a, bfr[nt >> 1][nt & 1], bfr[nt >> 1][(nt & 1) + 2]);
        }

        if (jt >= jend - 1) {
            int coff = jt * 64 - qblk * 128;
#pragma unroll
            for (int nt = 0; nt < 8; nt++) {
                int c0 = coff + nt * 8 + 2 * qid;
                if (c0 > r0)     sfr[nt][0] = -1e30f;
                if (c0 + 1 > r0) sfr[nt][1] = -1e30f;
                if (c0 > r1)     sfr[nt][2] = -1e30f;
                if (c0 + 1 > r1) sfr[nt][3] = -1e30f;
            }
        }

        float mx0 = -1e30f, mx1 = -1e30f;
#pragma unroll
        for (int nt = 0; nt < 8; nt++) {
            mx0 = fmaxf(mx0, fmaxf(sfr[nt][0], sfr[nt][1]));
            mx1 = fmaxf(mx1, fmaxf(sfr[nt][2], sfr[nt][3]));
        }
        mx0 = fmaxf(mx0, __shfl_xor_sync(0xffffffffu, mx0, 1));
        mx0 = fmaxf(mx0, __shfl_xor_sync(0xffffffffu, mx0, 2));
        mx1 = fmaxf(mx1, __shfl_xor_sync(0xffffffffu, mx1, 1));
        mx1 = fmaxf(mx1, __shfl_xor_sync(0xffffffffu, mx1, 2));
        float mn0 = fmaxf(m0, mx0), mn1 = fmaxf(m1, mx1);
        float al0 = ex2(m0 - mn0), al1 = ex2(m1 - mn1);
        m0 = mn0; m1 = mn1;

        uint32_t hp0[8], hp1[8];
        float sum0 = 0.f, sum1 = 0.f;
#pragma unroll
        for (int nt = 0; nt < 8; nt++) {
            float p00 = ex2(sfr[nt][0] - mn0), p01 = ex2(sfr[nt][1] - mn0);
            float p10 = ex2(sfr[nt][2] - mn1), p11 = ex2(sfr[nt][3] - mn1);
            sum0 += p00 + p01;
            sum1 += p10 + p11;
            hp0[nt] = packh2(p00, p01);
            hp1[nt] = packh2(p10, p11);
        }
        sum0 += __shfl_xor_sync(0xffffffffu, sum0, 1);
        sum0 += __shfl_xor_sync(0xffffffffu, sum0, 2);
        sum1 += __shfl_xor_sync(0xffffffffu, sum1, 1);
        sum1 += __shfl_xor_sync(0xffffffffu, sum1, 2);
        l0 = l0 * al0 + sum0;
        l1 = l1 * al1 + sum1;

#pragma unroll
        for (int nt = 0; nt < 16; nt++) {
            accO[nt][0] *= al0; accO[nt][1] *= al0;
            accO[nt][2] *= al1; accO[nt][3] *= al1;
        }

        int g = lane >> 3, ii = lane & 7;
#pragma unroll
        for (int ks = 0; ks < 4; ks++) {
            uint32_t pa[4] = { hp0[2 * ks], hp1[2 * ks],
                               hp0[2 * ks + 1], hp1[2 * ks + 1] };
#pragma unroll
            for (int np = 0; np < 8; np++) {
                uint32_t vb[4];
                LDMX4T(vb, bV + (uint32_t)(((ks * 16 + (g & 1) * 8 + ii) * AV
                                  + np * 16 + (g >> 1) * 8) * 2));
                mma_f16(accO[np * 2],     pa, vb[0], vb[1]);
                mma_f16(accO[np * 2 + 1], pa, vb[2], vb[3]);
            }
        }
    }

    float inv0 = 1.f / l0, inv1 = 1.f / l1;
#pragma unroll
    for (int nt = 0; nt < 16; nt++) {
        int col = h * 128 + nt * 8 + 2 * qid;
        *(__half2*)&out[(size_t)(t0 + r0) * 2048 + col] =
            __floats2half2_rn(accO[nt][0] * inv0, accO[nt][1] * inv0);
        *(__half2*)&out[(size_t)(t0 + r1) * 2048 + col] =
            __floats2half2_rn(accO[nt][2] * inv1, accO[nt][3] * inv1);
    }
}

// ---------------- launch -------------------------------------------------------
extern "C" void kernel_launch(void* const* d_in, const int* in_sizes, int n_in,
                              void* d_out, int out_size) {
    const float* x           = (const float*)d_in[0];
    const float* fc          = (const float*)d_in[1];
    const float* fs          = (const float*)d_in[2];
    const float* q_down_w    = (const float*)d_in[4];
    const float* q_norm_w    = (const float*)d_in[5];
    const float* q_up_nope_w = (const float*)d_in[6];
    const float* q_up_rope_w = (const float*)d_in[7];
    const float* kv_down_w   = (const float*)d_in[8];
    const float* kv_norm_w   = (const float*)d_in[9];
    const float* kv_up_w     = (const float*)d_in[10];
    const float* wo_w        = (const float*)d_in[11];
    float* out = (float*)d_out;

    __half *xh, *cqkv, *qh, *kroph, *kvh, *attnoh;
    __half *wqkd, *wqu, *wku, *wwo;
    float *rq, *rkv;
    cudaGetSymbolAddress((void**)&xh,     g_xh);
    cudaGetSymbolAddress((void**)&cqkv,   g_cqkv);
    cudaGetSymbolAddress((void**)&rq,     g_rq);
    cudaGetSymbolAddress((void**)&rkv,    g_rkv);
    cudaGetSymbolAddress((void**)&qh,     g_qh);
    cudaGetSymbolAddress((void**)&kroph,  g_kropeh);
    cudaGetSymbolAddress((void**)&kvh,    g_kvh);
    cudaGetSymbolAddress((void**)&attnoh, g_attnoh);
    cudaGetSymbolAddress((void**)&wqkd,   g_wqkd);
    cudaGetSymbolAddress((void**)&wqu,    g_wqu);
    cudaGetSymbolAddress((void**)&wku,    g_wku);
    cudaGetSymbolAddress((void**)&wwo,    g_wwo);

    cudaFuncSetAttribute(hgemm, cudaFuncAttributeMaxDynamicSharedMemorySize, HGEMM_SMEM);
    cudaFuncSetAttribute(attn2_kernel, cudaFuncAttributeMaxDynamicSharedMemorySize, ATT_SMEM);

    auto hc4 = [&](const float* s, __half* d, size_t n) {
        int S = (int)(n / 16);
        h_copy4<<<S / 256, 256>>>(s, d, S);
    };
    hc4(x, xh, (size_t)MTOK * DIM_);
    hc4(q_down_w, wqkd, (size_t)QLORA_ * DIM_);
    hc4(kv_down_w, wqkd + (size_t)QLORA_ * DIM_, (size_t)576 * DIM_);
    h_qup<<<3072, 128>>>(q_up_nope_w, q_up_rope_w, q_norm_w, wqu);
    h_wku<<<4096, 128>>>(kv_up_w, kv_norm_w, wku);
    hc4(wo_w, wwo, (size_t)DIM_ * 2048);

    dim3 blk(256);
    // merged down-proj: N=2112 -> cqkv (raw; norms applied later via row scales)
    hgemm<<<dim3((NQKV + 127) / 128, MTOK / 128), blk, HGEMM_SMEM>>>(
        xh, wqkd, nullptr, cqkv, MTOK, NQKV, DIM_, NQKV, DIM_,
        nullptr, 0, nullptr, nullptr);
    // per-token rms scales + k_rope rotation
    rownorm<<<MTOK, 256>>>(cqkv, fc, fs, rq, rkv, kroph);

    // q_up: A = cqkv (stride NQKV, K=1536, raw), row scale rq, fused RoPE
    hgemm<<<dim3(3072 / 128, MTOK / 128), blk, HGEMM_SMEM>>>(
        cqkv, wqu, nullptr, qh, MTOK, 3072, QLORA_, 3072, NQKV,
        rq, 1, fc, fs);

    // kv_up: A = cqkv cols 1536.. (stride NQKV, K=512, raw), row scale rkv
    hgemm<<<dim3(4096 / 128, MTOK / 128), blk, HGEMM_SMEM>>>(
        cqkv + QLORA_, wku, nullptr, kvh, MTOK, 4096, KVLORA_, 4096, NQKV,
        rkv, 0, nullptr, nullptr);

    // attention
    attn2_kernel<<<dim3(T_ / 128, H_, B_), 256, ATT_SMEM>>>(qh, kvh, kroph, attnoh);

    // wo
    hgemm<<<dim3(2048 / 128, MTOK / 128), blk, HGEMM_SMEM>>>(
        attnoh, wwo, out, nullptr, MTOK, 2048, 2048, 2048, 2048,
        nullptr, 0, nullptr, nullptr);
}

// round 14
// speedup vs baseline: 1.0116x; 1.0116x over previous
#include <cuda_runtime.h>
#include <cuda_fp16.h>
#include <cstdint>

// Problem constants
#define B_ 4
#define T_ 2048
#define DIM_ 2048
#define H_ 16
#define QLORA_ 1536
#define KVLORA_ 512
#define MTOK (B_ * T_)   // 8192
#define NQKV 2112        // merged q_down(1536) + kv_down(576) output width

// ---------------- scratch (device globals; no runtime allocation) -------------
__device__ __half g_xh[(size_t)MTOK * DIM_];
__device__ __half g_cqkv[(size_t)MTOK * NQKV];        // merged: [cq 1536 | ckv 512 | rope 64]
__device__ float  g_rq[MTOK];
__device__ float  g_rkv[MTOK];
__device__ __half g_qh[(size_t)MTOK * 3072];
__device__ __half g_kropeh[(size_t)MTOK * 64];
__device__ __half g_kvh[(size_t)MTOK * 4096];
__device__ __half g_attnoh[(size_t)MTOK * 2048];
__device__ __half g_wqkd[(size_t)NQKV * DIM_];
__device__ __half g_wqu[(size_t)3072 * QLORA_];
__device__ __half g_wku[(size_t)4096 * KVLORA_];
__device__ __half g_wwo[(size_t)DIM_ * 2048];

// ---------------- helpers ------------------------------------------------------
__device__ __forceinline__ float block_reduce_sum_256(float v) {
    __shared__ float red[8];
    int lane = threadIdx.x & 31, w = threadIdx.x >> 5;
#pragma unroll
    for (int o = 16; o; o >>= 1) v += __shfl_xor_sync(0xffffffffu, v, o);
    if (lane == 0) red[w] = v;
    __syncthreads();
    if (w == 0) {
        v = (lane < 8) ? red[lane] : 0.f;
#pragma unroll
        for (int o = 4; o; o >>= 1) v += __shfl_xor_sync(0xffffffffu, v, o);
        if (lane == 0) red[0] = v;
    }
    __syncthreads();
    return red[0];
}

__device__ __forceinline__ float ex2(float x) {
    float r;
    asm("ex2.approx.ftz.f32 %0, %1;" : "=f"(r) : "f"(x));
    return r;
}
__device__ __forceinline__ uint32_t smem_u32(const void* p) {
    uint32_t a;
    asm("{ .reg .u64 t; cvta.to.shared.u64 t, %1; cvt.u32.u64 %0, t; }"
        : "=r"(a) : "l"(p));
    return a;
}
__device__ __forceinline__ uint32_t packh2(float a, float b) {
    __half2 h = __floats2half2_rn(a, b);
    return *(uint32_t*)&h;
}
__device__ __forceinline__ uint2 pack4(float4 v) {
    return make_uint2(packh2(v.x, v.y), packh2(v.z, v.w));
}

#define LDMX4(r, addr) \
    asm volatile("ldmatrix.sync.aligned.m8n8.x4.shared.b16 {%0,%1,%2,%3}, [%4];" \
        : "=r"((r)[0]), "=r"((r)[1]), "=r"((r)[2]), "=r"((r)[3]) : "r"(addr))
#define LDMX4T(r, addr) \
    asm volatile("ldmatrix.sync.aligned.m8n8.x4.trans.shared.b16 {%0,%1,%2,%3}, [%4];" \
        : "=r"((r)[0]), "=r"((r)[1]), "=r"((r)[2]), "=r"((r)[3]) : "r"(addr))

__device__ __forceinline__ void mma_f16(float* c, const uint32_t* a,
                                        uint32_t b0, uint32_t b1) {
    asm volatile(
        "mma.sync.aligned.m16n8k16.row.col.f32.f16.f16.f32 "
        "{%0,%1,%2,%3},{%4,%5,%6,%7},{%8,%9},{%0,%1,%2,%3};\n"
        : "+f"(c[0]), "+f"(c[1]), "+f"(c[2]), "+f"(c[3])
        : "r"(a[0]), "r"(a[1]), "r"(a[2]), "r"(a[3]), "r"(b0), "r"(b1));
}

__device__ __forceinline__ void cpa16(uint32_t saddr, const void* src, bool v) {
    int sz = v ? 16 : 0;
    asm volatile("cp.async.cg.shared.global [%0], [%1], 16, %2;\n"
                 :: "r"(saddr), "l"(src), "r"(sz));
}

// ---------------- fused conversion kernel ----------------------------------------
// Block-range dispatch: [0,4096) x -> xh; [..768) qd; [..288) kd; [..1024) wo;
// [..3072) q_up interleave+fold; [..2048) kv_up fold. All 256-thread blocks.
#define QSC (0.07216878364870323f * 1.4426950408889634f)

__device__ __forceinline__ void copy4_body(const float* __restrict__ src,
                                           __half* __restrict__ dst, int S, int b) {
    int i = b * 256 + threadIdx.x;
    const float4* s4 = (const float4*)src;
    uint2* d2 = (uint2*)dst;
    float4 v0 = s4[i], v1 = s4[i + S], v2 = s4[i + 2 * S], v3 = s4[i + 3 * S];
    d2[i]         = pack4(v0);
    d2[i + S]     = pack4(v1);
    d2[i + 2 * S] = pack4(v2);
    d2[i + 3 * S] = pack4(v3);
}

__global__ void convert_all(
    const float* __restrict__ x, const float* __restrict__ qd,
    const float* __restrict__ kd, const float* __restrict__ wo,
    const float* __restrict__ nope, const float* __restrict__ rope,
    const float* __restrict__ qw, const float* __restrict__ ku,
    const float* __restrict__ kw,
    __half* __restrict__ xh, __half* __restrict__ wqkd,
    __half* __restrict__ wwo, __half* __restrict__ wqu, __half* __restrict__ wkuD)
{
    int b = blockIdx.x;
    if (b < 4096) { copy4_body(x, xh, 1048576, b); return; }           // 32MB x
    b -= 4096;
    if (b < 768) { copy4_body(qd, wqkd, 196608, b); return; }          // q_down w
    b -= 768;
    if (b < 288) { copy4_body(kd, wqkd + (size_t)QLORA_ * DIM_, 73728, b); return; }
    b -= 288;
    if (b < 1024) { copy4_body(wo, wwo, 262144, b); return; }          // wo w
    b -= 1024;
    if (b < 3072) {                                                    // q_up fold
        int r = b;
        int h = r / 192, d = r - h * 192;
        const float* src = (d < 128) ? nope + (size_t)(h * 128 + d) * QLORA_
                                     : rope + (size_t)(h * 64 + d - 128) * QLORA_;
        const float4* s4 = (const float4*)src;
        const float4* w4 = (const float4*)qw;
        uint2* o2 = (uint2*)(wqu + (size_t)r * QLORA_);
        for (int c = threadIdx.x; c < 384; c += 256) {
            float4 v = s4[c], w = w4[c];
            v.x *= QSC * w.x; v.y *= QSC * w.y; v.z *= QSC * w.z; v.w *= QSC * w.w;
            o2[c] = pack4(v);
        }
        return;
    }
    b -= 3072;
    {                                                                  // kv_up fold
        int r = b * 2 + (threadIdx.x >> 7);
        int i = threadIdx.x & 127;
        const float4* s4 = (const float4*)(ku + (size_t)r * KVLORA_);
        const float4* w4 = (const float4*)kw;
        uint2* o2 = (uint2*)(wkuD + (size_t)r * KVLORA_);
        float4 v = s4[i], w = w4[i];
        v.x *= w.x; v.y *= w.y; v.z *= w.z; v.w *= w.w;
        o2[i] = pack4(v);
    }
}
#define CONV_BLOCKS (4096 + 768 + 288 + 1024 + 3072 + 2048)

// ---------------- fp16 tensor-core GEMM (128x128 CTA, occ 2, strided A) ---------
#define HAS 40
#define HTILE_B (128 * HAS * 2)
#define HST_B (2 * HTILE_B)
#define HST 4
#define HGEMM_SMEM (HST * HST_B)

__global__ void __launch_bounds__(256, 2) hgemm(
    const __half* __restrict__ A, const __half* __restrict__ W,
    float* __restrict__ Cf, __half* __restrict__ Ch,
    int M, int N, int K, int ldc, int lda,
    const float* __restrict__ rowScale,
    int ropeOn, const float* __restrict__ fc, const float* __restrict__ fs)
{
    extern __shared__ __align__(16) char hsm[];
    uint32_t sbase = smem_u32(hsm);
    int tid = threadIdx.x, warp = tid >> 5, lane = tid & 31;
    int wm = warp >> 2, wn = warp & 3, grp = lane >> 2, qid = lane & 3;
    int bm = blockIdx.y * 128, bn = blockIdx.x * 128;

    float acc[4][4][4];
#pragma unroll
    for (int mt = 0; mt < 4; mt++)
#pragma unroll
        for (int nt = 0; nt < 4; nt++)
#pragma unroll
            for (int i = 0; i < 4; i++) acc[mt][nt][i] = 0.f;

    int lr = tid >> 2, lc = tid & 3;
    const __half* Ag0 = A + (size_t)(bm + lr) * lda + lc * 8;
    const __half* Ag1 = A + (size_t)(bm + lr + 64) * lda + lc * 8;
    int n0 = bn + lr, n1 = bn + lr + 64;
    bool v0 = n0 < N, v1 = n1 < N;
    const __half* Wg0 = W + (size_t)(v0 ? n0 : 0) * K + lc * 8;
    const __half* Wg1 = W + (size_t)(v1 ? n1 : 0) * K + lc * 8;
    uint32_t dA0 = sbase + lr * 80 + lc * 16;
    uint32_t dA1 = dA0 + 64 * 80;
    uint32_t dB0 = dA0 + HTILE_B;
    uint32_t dB1 = dB0 + 64 * 80;

    int NK = K >> 5;

    auto prefetch = [&](int kt) {
        uint32_t off = (uint32_t)((kt % HST) * HST_B);
        int ko = kt * 32;
        cpa16(dA0 + off, Ag0 + ko, true);
        cpa16(dA1 + off, Ag1 + ko, true);
        cpa16(dB0 + off, Wg0 + ko, v0);
        cpa16(dB1 + off, Wg1 + ko, v1);
    };

#pragma unroll
    for (int i = 0; i < HST - 1; i++) {
        if (i < NK) prefetch(i);
        asm volatile("cp.async.commit_group;\n");
    }

    int lrow = lane & 15;
    for (int kt = 0; kt < NK; kt++) {
        asm volatile("cp.async.wait_group 2;\n");
        __syncthreads();
        if (kt + HST - 1 < NK) prefetch(kt + HST - 1);
        asm volatile("cp.async.commit_group;\n");

        uint32_t sA = sbase + (uint32_t)((kt % HST) * HST_B);
        uint32_t sB = sA + HTILE_B;
#pragma unroll
        for (int ks = 0; ks < 2; ks++) {
            uint32_t ko = (uint32_t)((ks * 16 + 8 * (lane >> 4)) * 2);
            uint32_t a[4][4], bfr[2][4];
#pragma unroll
            for (int mt = 0; mt < 4; mt++)
                LDMX4(a[mt], sA + (uint32_t)((wm * 64 + mt * 16 + lrow) * 80) + ko);
#pragma unroll
            for (int p = 0; p < 2; p++)
                LDMX4(bfr[p], sB + (uint32_t)((wn * 32 + p * 16 + lrow) * 80) + ko);
#pragma unroll
            for (int mt = 0; mt < 4; mt++)
#pragma unroll
                for (int nt = 0; nt < 4; nt++)
                    mma_f16(acc[mt][nt], a[mt],
                            bfr[nt >> 1][nt & 1], bfr[nt >> 1][(nt & 1) + 2]);
        }
    }

#pragma unroll
    for (int mt = 0; mt < 4; mt++) {
        int row = bm + wm * 64 + mt * 16 + grp;
        int t0r = row & (T_ - 1), t1r = (row + 8) & (T_ - 1);
        float rs0 = 1.f, rs1 = 1.f;
        if (rowScale) { rs0 = rowScale[row]; rs1 = rowScale[row + 8]; }
#pragma unroll
        for (int nt = 0; nt < 4; nt++) {
            int n = bn + wn * 32 + nt * 8 + 2 * qid;
            if (n < N) {
                float o0 = acc[mt][nt][0] * rs0, o1 = acc[mt][nt][1] * rs0;
                float o2 = acc[mt][nt][2] * rs1, o3 = acc[mt][nt][3] * rs1;
                if (ropeOn) {
                    int d = n % 192;
                    if (d >= 128) {
                        int i = (d - 128) >> 1;
                        float c0 = fc[t0r * 32 + i], s0 = fs[t0r * 32 + i];
                        float c1 = fc[t1r * 32 + i], s1 = fs[t1r * 32 + i];
                        float a0 = o0 * c0 - o1 * s0, a1 = o0 * s0 + o1 * c0;
                        float a2 = o2 * c1 - o3 * s1, a3 = o2 * s1 + o3 * c1;
                        o0 = a0; o1 = a1; o2 = a2; o3 = a3;
                    }
                }
                if (Cf) {
                    *(float2*)&Cf[(size_t)row * ldc + n] = make_float2(o0, o1);
                    *(float2*)&Cf[(size_t)(row + 8) * ldc + n] = make_float2(o2, o3);
                } else {
                    *(__half2*)&Ch[(size_t)row * ldc + n] = __floats2half2_rn(o0, o1);
                    *(__half2*)&Ch[(size_t)(row + 8) * ldc + n] = __floats2half2_rn(o2, o3);
                }
            }
        }
    }
}

// ---------------- rownorm: per-token rms scales + k_rope rotation ---------------
__global__ void rownorm(const __half* __restrict__ merged,
                        const float* __restrict__ fc, const float* __restrict__ fs,
                        float* __restrict__ rq, float* __restrict__ rkv,
                        __half* __restrict__ kr) {
    int tok = blockIdx.x;
    const __half* src = merged + (size_t)tok * NQKV;
    float sq = 0.f;
    for (int i = threadIdx.x; i < QLORA_; i += 256) {
        float v = __half2float(src[i]); sq += v * v;
    }
    sq = block_reduce_sum_256(sq);
    float skv = 0.f;
    for (int i = threadIdx.x; i < KVLORA_; i += 256) {
        float v = __half2float(src[QLORA_ + i]); skv += v * v;
    }
    skv = block_reduce_sum_256(skv);
    if (threadIdx.x == 0) {
        rq[tok]  = rsqrtf(sq / (float)QLORA_ + 1e-6f);
        rkv[tok] = rsqrtf(skv / (float)KVLORA_ + 1e-6f);
    }
    if (threadIdx.x < 32) {
        int t = tok & (T_ - 1);
        int i = threadIdx.x;
        float x0 = __half2float(src[2048 + 2 * i]);
        float x1 = __half2float(src[2048 + 2 * i + 1]);
        float c = fc[t * 32 + i], s = fs[t * 32 + i];
        ((__half2*)kr)[(size_t)tok * 32 + i] =
            __floats2half2_rn(x0 * c - x1 * s, x0 * s + x1 * c);
    }
}

// ---------------- fp16 flash attention, Br=128, Bc=64, reg P + hoisted Q --------
#define AQ 200
#define AK 200
#define AV 136
#define ATT_SMEM ((128*AQ + 2*64*AK + 2*64*AV) * 2)

__global__ void __launch_bounds__(256, 1) attn2_kernel(
    const __half* __restrict__ qh, const __half* __restrict__ kvh,
    const __half* __restrict__ kroph, __half* __restrict__ out)
{
    extern __shared__ __align__(16) char smraw[];
    __half* hQ = (__half*)smraw;           // [128][AQ]
    __half* hK = hQ + 128 * AQ;            // [2][64][AK]
    __half* hV = hK + 2 * 64 * AK;         // [2][64][AV]
    uint32_t uQ = smem_u32(hQ), uK = smem_u32(hK), uV = smem_u32(hV);

    int b = blockIdx.z, h = blockIdx.y;
    int qblk = gridDim.x - 1 - blockIdx.x;   // big-work CTAs first
    int tid = threadIdx.x;
    int warp = tid >> 5, lane = tid & 31;
    int grp = lane >> 2, qid = lane & 3, lrow = lane & 15;
    int w16 = warp * 16;
    int t0 = b * T_ + qblk * 128;
    int r0 = w16 + grp, r1 = r0 + 8;

    auto prefKV = [&](int jt) {
        int kb = b * T_ + jt * 64;
        int s = jt & 1;
        uint32_t bK = uK + (uint32_t)(s * 64 * AK * 2);
        uint32_t bV = uV + (uint32_t)(s * 64 * AV * 2);
#pragma unroll
        for (int i = 0; i < 4; i++) {
            int idx = tid + i * 256, c = idx >> 4, f = idx & 15;
            cpa16(bK + (uint32_t)((c * AK + f * 8) * 2),
                  kvh + (size_t)(kb + c) * 4096 + h * 256 + f * 8, true);
        }
#pragma unroll
        for (int i = 0; i < 2; i++) {
            int idx = tid + i * 256, c = idx >> 3, f = idx & 7;
            cpa16(bK + (uint32_t)((c * AK + 128 + f * 8) * 2),
                  kroph + (size_t)(kb + c) * 64 + f * 8, true);
        }
#pragma unroll
        for (int i = 0; i < 4; i++) {
            int idx = tid + i * 256, c = idx >> 4, f = idx & 15;
            cpa16(bV + (uint32_t)((c * AV + f * 8) * 2),
                  kvh + (size_t)(kb + c) * 4096 + h * 256 + 128 + f * 8, true);
        }
    };

    int jend = 2 * qblk + 1;
    prefKV(0);
    asm volatile("cp.async.commit_group;\n");

    // stage Q tile [128 x 192] to smem, then hoist this warp's fragments to regs
    for (int idx = tid; idx < 128 * 24; idx += 256) {
        int r = idx / 24, f = idx - r * 24;
        *(uint4*)&hQ[r * AQ + f * 8] =
            *(const uint4*)&qh[(size_t)(t0 + r) * 3072 + h * 192 + f * 8];
    }
    __syncthreads();
    uint32_t qa[12][4];
#pragma unroll
    for (int ks = 0; ks < 12; ks++) {
        uint32_t ko = (uint32_t)((ks * 16 + 8 * (lane >> 4)) * 2);
        LDMX4(qa[ks], uQ + (uint32_t)((w16 + lrow) * AQ * 2) + ko);
    }

    float m0 = -1e30f, m1 = -1e30f, l0 = 0.f, l1 = 0.f;
    float accO[16][4];
#pragma unroll
    for (int nt = 0; nt < 16; nt++)
#pragma unroll
        for (int i = 0; i < 4; i++) accO[nt][i] = 0.f;

    for (int jt = 0; jt <= jend; jt++) {
        __syncthreads();                       // prev iter done with s^1 buffer
        if (jt < jend) prefKV(jt + 1);
        asm volatile("cp.async.commit_group;\n");
        if (jt < jend) { asm volatile("cp.async.wait_group 1;\n"); }
        else           { asm volatile("cp.async.wait_group 0;\n"); }
        __syncthreads();                       // tile jt visible

        int s = jt & 1;
        uint32_t bK = uK + (uint32_t)(s * 64 * AK * 2);
        uint32_t bV = uV + (uint32_t)(s * 64 * AV * 2);

        float sfr[8][4];
#pragma unroll
        for (int nt = 0; nt < 8; nt++)
#pragma unroll
            for (int i = 0; i < 4; i++) sfr[nt][i] = 0.f;
#pragma unroll
        for (int ks = 0; ks < 12; ks++) {
            uint32_t ko = (uint32_t)((ks * 16 + 8 * (lane >> 4)) * 2);
            uint32_t bfr[4][4];
#pragma unroll
            for (int p = 0; p < 4; p++)
                LDMX4(bfr[p], bK + (uint32_t)((p * 16 + lrow) * AK * 2) + ko);
#pragma unroll
            for (int nt = 0; nt < 8; nt++)
                mma_f16(sfr[nt], qa[ks], bfr[nt >> 1][nt & 1], bfr[nt >> 1][(nt & 1) + 2]);
        }

        if (jt >= jend - 1) {
            int coff = jt * 64 - qblk * 128;
#pragma unroll
            for (int nt = 0; nt < 8; nt++) {
                int c0 = coff + nt * 8 + 2 * qid;
                if (c0 > r0)     sfr[nt][0] = -1e30f;
                if (c0 + 1 > r0) sfr[nt][1] = -1e30f;
                if (c0 > r1)     sfr[nt][2] = -1e30f;
                if (c0 + 1 > r1) sfr[nt][3] = -1e30f;
            }
        }

        float mx0 = -1e30f, mx1 = -1e30f;
#pragma unroll
        for (int nt = 0; nt < 8; nt++) {
            mx0 = fmaxf(mx0, fmaxf(sfr[nt][0], sfr[nt][1]));
            mx1 = fmaxf(mx1, fmaxf(sfr[nt][2], sfr[nt][3]));
        }
        mx0 = fmaxf(mx0, __shfl_xor_sync(0xffffffffu, mx0, 1));
        mx0 = fmaxf(mx0, __shfl_xor_sync(0xffffffffu, mx0, 2));
        mx1 = fmaxf(mx1, __shfl_xor_sync(0xffffffffu, mx1, 1));
        mx1 = fmaxf(mx1, __shfl_xor_sync(0xffffffffu, mx1, 2));
        float mn0 = fmaxf(m0, mx0), mn1 = fmaxf(m1, mx1);
        float al0 = ex2(m0 - mn0), al1 = ex2(m1 - mn1);
        m0 = mn0; m1 = mn1;

        uint32_t hp0[8], hp1[8];
        float sum0 = 0.f, sum1 = 0.f;
#pragma unroll
        for (int nt = 0; nt < 8; nt++) {
            float p00 = ex2(sfr[nt][0] - mn0), p01 = ex2(sfr[nt][1] - mn0);
            float p10 = ex2(sfr[nt][2] - mn1), p11 = ex2(sfr[nt][3] - mn1);
            sum0 += p00 + p01;
            sum1 += p10 + p11;
            hp0[nt] = packh2(p00, p01);
            hp1[nt] = packh2(p10, p11);
        }
        sum0 += __shfl_xor_sync(0xffffffffu, sum0, 1);
        sum0 += __shfl_xor_sync(0xffffffffu, sum0, 2);
        sum1 += __shfl_xor_sync(0xffffffffu, sum1, 1);
        sum1 += __shfl_xor_sync(0xffffffffu, sum1, 2);
        l0 = l0 * al0 + sum0;
        l1 = l1 * al1 + sum1;

#pragma unroll
        for (int nt = 0; nt < 16; nt++) {
            accO[nt][0] *= al0; accO[nt][1] *= al0;
            accO[nt][2] *= al1; accO[nt][3] *= al1;
        }

        int g = lane >> 3, ii = lane & 7;
#pragma unroll
        for (int ks = 0; ks < 4; ks++) {
            uint32_t pa[4] = { hp0[2 * ks], hp1[2 * ks],
                               hp0[2 * ks + 1], hp1[2 * ks + 1] };
#pragma unroll
            for (int np = 0; np < 8; np++) {
                uint32_t vb[4];
                LDMX4T(vb, bV + (uint32_t)(((ks * 16 + (g & 1) * 8 + ii) * AV
                                  + np * 16 + (g >> 1) * 8) * 2));
                mma_f16(accO[np * 2],     pa, vb[0], vb[1]);
                mma_f16(accO[np * 2 + 1], pa, vb[2], vb[3]);
            }
        }
    }

    float inv0 = 1.f / l0, inv1 = 1.f / l1;
#pragma unroll
    for (int nt = 0; nt < 16; nt++) {
        int col = h * 128 + nt * 8 + 2 * qid;
        *(__half2*)&out[(size_t)(t0 + r0) * 2048 + col] =
            __floats2half2_rn(accO[nt][0] * inv0, accO[nt][1] * inv0);
        *(__half2*)&out[(size_t)(t0 + r1) * 2048 + col] =
            __floats2half2_rn(accO[nt][2] * inv1, accO[nt][3] * inv1);
    }
}

// ---------------- launch -------------------------------------------------------
extern "C" void kernel_launch(void* const* d_in, const int* in_sizes, int n_in,
                              void* d_out, int out_size) {
    const float* x           = (const float*)d_in[0];
    const float* fc          = (const float*)d_in[1];
    const float* fs          = (const float*)d_in[2];
    const float* q_down_w    = (const float*)d_in[4];
    const float* q_norm_w    = (const float*)d_in[5];
    const float* q_up_nope_w = (const float*)d_in[6];
    const float* q_up_rope_w = (const float*)d_in[7];
    const float* kv_down_w   = (const float*)d_in[8];
    const float* kv_norm_w   = (const float*)d_in[9];
    const float* kv_up_w     = (const float*)d_in[10];
    const float* wo_w        = (const float*)d_in[11];
    float* out = (float*)d_out;

    __half *xh, *cqkv, *qh, *kroph, *kvh, *attnoh;
    __half *wqkd, *wqu, *wku, *wwo;
    float *rq, *rkv;
    cudaGetSymbolAddress((void**)&xh,     g_xh);
    cudaGetSymbolAddress((void**)&cqkv,   g_cqkv);
    cudaGetSymbolAddress((void**)&rq,     g_rq);
    cudaGetSymbolAddress((void**)&rkv,    g_rkv);
    cudaGetSymbolAddress((void**)&qh,     g_qh);
    cudaGetSymbolAddress((void**)&kroph,  g_kropeh);
    cudaGetSymbolAddress((void**)&kvh,    g_kvh);
    cudaGetSymbolAddress((void**)&attnoh, g_attnoh);
    cudaGetSymbolAddress((void**)&wqkd,   g_wqkd);
    cudaGetSymbolAddress((void**)&wqu,    g_wqu);
    cudaGetSymbolAddress((void**)&wku,    g_wku);
    cudaGetSymbolAddress((void**)&wwo,    g_wwo);

    cudaFuncSetAttribute(hgemm, cudaFuncAttributeMaxDynamicSharedMemorySize, HGEMM_SMEM);
    cudaFuncSetAttribute(attn2_kernel, cudaFuncAttributeMaxDynamicSharedMemorySize, ATT_SMEM);

    // all conversions in one launch
    convert_all<<<CONV_BLOCKS, 256>>>(
        x, q_down_w, kv_down_w, wo_w, q_up_nope_w, q_up_rope_w,
        q_norm_w, kv_up_w, kv_norm_w,
        xh, wqkd, wwo, wqu, wku);

    dim3 blk(256);
    // merged down-proj: N=2112 -> cqkv (raw; norms applied via row scales)
    hgemm<<<dim3((NQKV + 127) / 128, MTOK / 128), blk, HGEMM_SMEM>>>(
        xh, wqkd, nullptr, cqkv, MTOK, NQKV, DIM_, NQKV, DIM_,
        nullptr, 0, nullptr, nullptr);
    rownorm<<<MTOK, 256>>>(cqkv, fc, fs, rq, rkv, kroph);

    // q_up: A = cqkv (stride NQKV, K=1536, raw), row scale rq, fused RoPE
    hgemm<<<dim3(3072 / 128, MTOK / 128), blk, HGEMM_SMEM>>>(
        cqkv, wqu, nullptr, qh, MTOK, 3072, QLORA_, 3072, NQKV,
        rq, 1, fc, fs);

    // kv_up: A = cqkv cols 1536.. (stride NQKV, K=512, raw), row scale rkv
    hgemm<<<dim3(4096 / 128, MTOK / 128), blk, HGEMM_SMEM>>>(
        cqkv + QLORA_, wku, nullptr, kvh, MTOK, 4096, KVLORA_, 4096, NQKV,
        rkv, 0, nullptr, nullptr);

    // attention
    attn2_kernel<<<dim3(T_ / 128, H_, B_), 256, ATT_SMEM>>>(qh, kvh, kroph, attnoh);

    // wo
    hgemm<<<dim3(2048 / 128, MTOK / 128), blk, HGEMM_SMEM>>>(
        attnoh, wwo, out, nullptr, MTOK, 2048, 2048, 2048, 2048,
        nullptr, 0, nullptr, nullptr);
}